// round 6
// baseline (speedup 1.0000x reference)
#include <cuda_runtime.h>
#include <cuda_fp16.h>
#include <cstdint>

// ============================================================================
// SparseLinear: out[8192,4096] = x[8192,4096] @ (weight*mask)[4096,4096]^T
// fp16 staging + dense mma.sync.m16n8k16 GEMM, fp32 accumulation.
// R6: pin the fast ptxas allocation. Empirics across R2-R5: reg cap 64
// (regs=62) -> 288us GEMM; uncapped/high (106-128 regs) -> 600-790us.
// Single change vs R5: __launch_bounds__(256, 4) => 64-reg cap.
// (Occupancy is smem-capped at 2 CTAs/SM either way.)
// ============================================================================

#define MDIM 8192
#define NDIM 4096
#define KDIM 4096
#define BM 128
#define BN 128
#define BK 64
#define NKT (KDIM / BK)   // 64
#define THREADS 256
#define STAGES 3

__device__ __align__(1024) __half g_A[(size_t)MDIM * KDIM];  // x as fp16
__device__ __align__(1024) __half g_B[(size_t)NDIM * KDIM];  // (w*mask) as fp16
__device__ int g_mask_mode;  // 0 = uint8, 1 = int32, 2 = float32

// ---------------------------------------------------------------------------
// Helpers
// ---------------------------------------------------------------------------
__device__ __forceinline__ uint32_t smem_u32(const void* p) {
    uint32_t a;
    asm("{ .reg .u64 t; cvta.to.shared.u64 t, %1; cvt.u32.u64 %0, t; }"
        : "=r"(a) : "l"(p));
    return a;
}

__device__ __forceinline__ void cp_async16(uint32_t smem, const void* gmem) {
    asm volatile("cp.async.cg.shared.global [%0], [%1], 16;"
                 :: "r"(smem), "l"(gmem) : "memory");
}

// ---------------------------------------------------------------------------
// Mask dtype detection: coalesced uint4 scan of first 64KB.
// ---------------------------------------------------------------------------
__global__ void detect_mask_kernel(const uint4* __restrict__ m) {
    __shared__ int cnt[4];
    if (threadIdx.x < 4) cnt[threadIdx.x] = 0;
    __syncthreads();
    int local[4] = {0, 0, 0, 0};
#pragma unroll
    for (int i = 0; i < 16; i++) {
        uint4 v = m[threadIdx.x + i * 256];
        uint32_t ws[4] = {v.x, v.y, v.z, v.w};
#pragma unroll
        for (int q = 0; q < 4; q++) {
#pragma unroll
            for (int bpos = 0; bpos < 4; bpos++)
                local[bpos] += ((ws[q] >> (8 * bpos)) & 0xFF) ? 1 : 0;
        }
    }
#pragma unroll
    for (int j = 0; j < 4; j++)
        if (local[j]) atomicAdd(&cnt[j], local[j]);
    __syncthreads();
    if (threadIdx.x == 0) {
        int mode;
        if (cnt[1] == 0 && cnt[2] == 0 && cnt[3] == 0) mode = 1;       // int32
        else if (cnt[0] == 0 && cnt[1] == 0)          mode = 2;       // float32
        else                                           mode = 0;       // uint8
        g_mask_mode = mode;
    }
}

// ---------------------------------------------------------------------------
// Prep: f32 -> fp16 conversions
// ---------------------------------------------------------------------------
__global__ void convert_x_kernel(const float* __restrict__ x) {
    const size_t n4 = (size_t)MDIM * KDIM / 4;
    const float4* x4 = (const float4*)x;
    __half2* o = (__half2*)g_A;
    size_t stride = (size_t)gridDim.x * blockDim.x;
    for (size_t j = (size_t)blockIdx.x * blockDim.x + threadIdx.x; j < n4; j += stride) {
        float4 v = x4[j];
        o[2 * j + 0] = __floats2half2_rn(v.x, v.y);
        o[2 * j + 1] = __floats2half2_rn(v.z, v.w);
    }
}

__global__ void convert_w_kernel(const float* __restrict__ w,
                                 const void* __restrict__ mask) {
    const size_t n4 = (size_t)NDIM * KDIM / 4;
    const float4* w4 = (const float4*)w;
    __half2* o = (__half2*)g_B;
    const int mode = g_mask_mode;
    size_t stride = (size_t)gridDim.x * blockDim.x;
    for (size_t j = (size_t)blockIdx.x * blockDim.x + threadIdx.x; j < n4; j += stride) {
        float4 v = w4[j];
        bool k0, k1, k2, k3;
        if (mode == 0) {
            uchar4 m = ((const uchar4*)mask)[j];
            k0 = m.x; k1 = m.y; k2 = m.z; k3 = m.w;
        } else if (mode == 1) {
            int4 m = ((const int4*)mask)[j];
            k0 = m.x; k1 = m.y; k2 = m.z; k3 = m.w;
        } else {
            float4 m = ((const float4*)mask)[j];
            k0 = m.x != 0.f; k1 = m.y != 0.f; k2 = m.z != 0.f; k3 = m.w != 0.f;
        }
        float a = k0 ? v.x : 0.0f;
        float b = k1 ? v.y : 0.0f;
        float c = k2 ? v.z : 0.0f;
        float d = k3 ? v.w : 0.0f;
        o[2 * j + 0] = __floats2half2_rn(a, b);
        o[2 * j + 1] = __floats2half2_rn(c, d);
    }
}

// ---------------------------------------------------------------------------
// GEMM kernel: D[M,N] = A[M,K] @ B[N,K]^T   (mma.sync m16n8k16, fp32 acc)
// 8 warps as 2(M) x 4(N); warp tile 64M x 32N.
// ---------------------------------------------------------------------------
#define STAGE_BYTES (BM * 128 + BN * 128)             // 16KB A + 16KB B
#define SMEM_DYN_BYTES (STAGES * STAGE_BYTES + 1024)

__global__ void __launch_bounds__(THREADS, 4)   // 4 => 64-reg cap (R2-class binary)
sparse_gemm_kernel(float* __restrict__ out) {
    extern __shared__ char dsmem[];
    const int tid = threadIdx.x;
    const int wid = tid >> 5;
    const int lid = tid & 31;
    const int nt = blockIdx.x;   // N tile
    const int mt = blockIdx.y;   // M tile

    const uint32_t tiles = (smem_u32(dsmem) + 1023u) & ~1023u;

    const __half* gA_base = g_A + (size_t)mt * BM * KDIM;
    const __half* gB_base = g_B + (size_t)nt * BN * KDIM;

    // Tile loader: 1024 x 16B chunks per operand; SW128 swizzle.
    auto load_tile = [&](int kt, int stage) {
        const uint32_t sA = tiles + stage * STAGE_BYTES;
        const uint32_t sB = sA + BM * 128;
        const __half* gA = gA_base + kt * BK;
        const __half* gB = gB_base + kt * BK;
#pragma unroll
        for (int i = 0; i < 4; i++) {
            int c = tid + i * THREADS;        // 0..1023
            int row = c >> 3;
            int col = c & 7;                  // 16B chunk within 128B row
            uint32_t off = (uint32_t)(row << 7) | (uint32_t)(col << 4);
            uint32_t sw = off ^ ((off >> 3) & 0x70);
            size_t goff = (size_t)row * KDIM + col * 8;
            cp_async16(sA + sw, gA + goff);
            cp_async16(sB + sw, gB + goff);
        }
        asm volatile("cp.async.commit_group;" ::: "memory");
    };

    const int wm = wid & 1;          // 0..1
    const int wn = wid >> 1;         // 0..3
    const int m_base = wm * 64;
    const int n_base = wn * 32;

    float acc[4][4][4];              // [mi][n8][reg]
#pragma unroll
    for (int i = 0; i < 4; i++)
#pragma unroll
        for (int j = 0; j < 4; j++)
#pragma unroll
            for (int q = 0; q < 4; q++) acc[i][j][q] = 0.0f;

    // Per-lane base byte offsets inside a tile (pre-swizzle):
    const uint32_t baseA_off = (uint32_t)(m_base + (lid & 15)) * 128u + (uint32_t)(lid >> 4) * 16u;
    const uint32_t baseB_off = (uint32_t)(n_base + ((lid >> 4) << 3) + (lid & 7)) * 128u +
                               (uint32_t)((lid >> 3) & 1) * 16u;

    load_tile(0, 0);
    load_tile(1, 1);

    for (int kt = 0; kt < NKT; kt++) {
        const int stage = kt % STAGES;
        if (kt < NKT - 2) asm volatile("cp.async.wait_group 1;" ::: "memory");
        else              asm volatile("cp.async.wait_group 0;" ::: "memory");
        __syncthreads();

        if (kt + 2 < NKT) load_tile(kt + 2, (kt + 2) % STAGES);

        const uint32_t sA = tiles + stage * STAGE_BYTES;
        const uint32_t sB = sA + BM * 128;

#pragma unroll
        for (int ks = 0; ks < 4; ks++) {
            uint32_t a[4][4];
#pragma unroll
            for (int mi = 0; mi < 4; mi++) {
                uint32_t off = baseA_off + (uint32_t)mi * 2048u + (uint32_t)ks * 32u;
                uint32_t addr = sA + (off ^ ((off >> 3) & 0x70));
                asm volatile("ldmatrix.sync.aligned.m8n8.x4.shared.b16 {%0,%1,%2,%3}, [%4];"
                             : "=r"(a[mi][0]), "=r"(a[mi][1]), "=r"(a[mi][2]), "=r"(a[mi][3])
                             : "r"(addr));
            }
            uint32_t b[2][4];
#pragma unroll
            for (int nj = 0; nj < 2; nj++) {
                uint32_t off = baseB_off + (uint32_t)nj * 2048u + (uint32_t)ks * 32u;
                uint32_t addr = sB + (off ^ ((off >> 3) & 0x70));
                asm volatile("ldmatrix.sync.aligned.m8n8.x4.shared.b16 {%0,%1,%2,%3}, [%4];"
                             : "=r"(b[nj][0]), "=r"(b[nj][1]), "=r"(b[nj][2]), "=r"(b[nj][3])
                             : "r"(addr));
            }
#pragma unroll
            for (int mi = 0; mi < 4; mi++) {
#pragma unroll
                for (int n8 = 0; n8 < 4; n8++) {
                    uint32_t b0 = b[n8 >> 1][(n8 & 1) * 2 + 0];
                    uint32_t b1 = b[n8 >> 1][(n8 & 1) * 2 + 1];
                    asm volatile(
                        "mma.sync.aligned.m16n8k16.row.col.f32.f16.f16.f32 "
                        "{%0,%1,%2,%3}, {%4,%5,%6,%7}, {%8,%9}, {%0,%1,%2,%3};"
                        : "+f"(acc[mi][n8][0]), "+f"(acc[mi][n8][1]),
                          "+f"(acc[mi][n8][2]), "+f"(acc[mi][n8][3])
                        : "r"(a[mi][0]), "r"(a[mi][1]), "r"(a[mi][2]), "r"(a[mi][3]),
                          "r"(b0), "r"(b1));
                }
            }
        }
    }

    // Epilogue: direct f32 stores.
    const int tg = lid >> 2;            // 0..7
    const int tc = (lid & 3) * 2;
    float* obase = out + (size_t)(mt * BM + m_base) * NDIM + nt * BN + n_base;
#pragma unroll
    for (int mi = 0; mi < 4; mi++) {
#pragma unroll
        for (int n8 = 0; n8 < 4; n8++) {
            int r0 = mi * 16 + tg;
            int c0 = n8 * 8 + tc;
            float2 v0 = make_float2(acc[mi][n8][0], acc[mi][n8][1]);
            float2 v1 = make_float2(acc[mi][n8][2], acc[mi][n8][3]);
            *(float2*)(obase + (size_t)r0 * NDIM + c0) = v0;
            *(float2*)(obase + (size_t)(r0 + 8) * NDIM + c0) = v1;
        }
    }
}

// ---------------------------------------------------------------------------
// Launch
// ---------------------------------------------------------------------------
extern "C" void kernel_launch(void* const* d_in, const int* in_sizes, int n_in,
                              void* d_out, int out_size) {
    const float* x = (const float*)d_in[0];
    const float* w = (const float*)d_in[1];
    const void* mask = d_in[2];
    float* out = (float*)d_out;

    cudaFuncSetAttribute(sparse_gemm_kernel,
                         cudaFuncAttributeMaxDynamicSharedMemorySize,
                         SMEM_DYN_BYTES);

    detect_mask_kernel<<<1, 256>>>((const uint4*)mask);
    convert_x_kernel<<<4096, 256>>>(x);
    convert_w_kernel<<<2048, 256>>>(w, mask);

    dim3 grid(NDIM / BN, MDIM / BM);  // (32, 64)
    sparse_gemm_kernel<<<grid, THREADS, SMEM_DYN_BYTES>>>(out);
}

// round 7
// speedup vs baseline: 8.4772x; 8.4772x over previous
#include <cuda_runtime.h>
#include <cuda_fp16.h>
#include <cstdint>

// ============================================================================
// SparseLinear: out[8192,4096] = x[8192,4096] @ (weight*mask)[4096,4096]^T
// fp16 staging + dense GEMM, fp32 accumulation.
//
// R7 insight: harness builds BOTH compute_103 PTX and an sm_103a cubin.
// R2's fast 288us run (regs=62, smem=32 static, tensor=39.9%) was the
// tcgen05 branch from the sm_103a cubin. Restore it, with a deeper pipeline:
// 3 smem stages + 3 mbarriers, MMA completion wait lagged one tile.
// mma.sync fallback under #else only so the compute_103 PTX pass assembles.
// ============================================================================

#define MDIM 8192
#define NDIM 4096
#define KDIM 4096
#define BM 128
#define BN 128
#define BK 64
#define NKT (KDIM / BK)   // 64
#define THREADS 256
#define STAGES 3

__device__ __align__(1024) __half g_A[(size_t)MDIM * KDIM];  // x as fp16
__device__ __align__(1024) __half g_B[(size_t)NDIM * KDIM];  // (w*mask) as fp16
__device__ int g_mask_mode;  // 0 = uint8, 1 = int32, 2 = float32

// ---------------------------------------------------------------------------
// Helpers
// ---------------------------------------------------------------------------
__device__ __forceinline__ uint32_t smem_u32(const void* p) {
    uint32_t a;
    asm("{ .reg .u64 t; cvta.to.shared.u64 t, %1; cvt.u32.u64 %0, t; }"
        : "=r"(a) : "l"(p));
    return a;
}

__device__ __forceinline__ void cp_async16(uint32_t smem, const void* gmem) {
    asm volatile("cp.async.cg.shared.global [%0], [%1], 16;"
                 :: "r"(smem), "l"(gmem) : "memory");
}

// ---------------------------------------------------------------------------
// Mask dtype detection: coalesced uint4 scan of first 64KB.
// ---------------------------------------------------------------------------
__global__ void detect_mask_kernel(const uint4* __restrict__ m) {
    __shared__ int cnt[4];
    if (threadIdx.x < 4) cnt[threadIdx.x] = 0;
    __syncthreads();
    int local[4] = {0, 0, 0, 0};
#pragma unroll
    for (int i = 0; i < 16; i++) {
        uint4 v = m[threadIdx.x + i * 256];
        uint32_t ws[4] = {v.x, v.y, v.z, v.w};
#pragma unroll
        for (int q = 0; q < 4; q++) {
#pragma unroll
            for (int bpos = 0; bpos < 4; bpos++)
                local[bpos] += ((ws[q] >> (8 * bpos)) & 0xFF) ? 1 : 0;
        }
    }
#pragma unroll
    for (int j = 0; j < 4; j++)
        if (local[j]) atomicAdd(&cnt[j], local[j]);
    __syncthreads();
    if (threadIdx.x == 0) {
        int mode;
        if (cnt[1] == 0 && cnt[2] == 0 && cnt[3] == 0) mode = 1;       // int32
        else if (cnt[0] == 0 && cnt[1] == 0)          mode = 2;       // float32
        else                                           mode = 0;       // uint8
        g_mask_mode = mode;
    }
}

// ---------------------------------------------------------------------------
// Prep: f32 -> fp16 conversions
// ---------------------------------------------------------------------------
__global__ void convert_x_kernel(const float* __restrict__ x) {
    const size_t n4 = (size_t)MDIM * KDIM / 4;
    const float4* x4 = (const float4*)x;
    __half2* o = (__half2*)g_A;
    size_t stride = (size_t)gridDim.x * blockDim.x;
    for (size_t j = (size_t)blockIdx.x * blockDim.x + threadIdx.x; j < n4; j += stride) {
        float4 v = x4[j];
        o[2 * j + 0] = __floats2half2_rn(v.x, v.y);
        o[2 * j + 1] = __floats2half2_rn(v.z, v.w);
    }
}

__global__ void convert_w_kernel(const float* __restrict__ w,
                                 const void* __restrict__ mask) {
    const size_t n4 = (size_t)NDIM * KDIM / 4;
    const float4* w4 = (const float4*)w;
    __half2* o = (__half2*)g_B;
    const int mode = g_mask_mode;
    size_t stride = (size_t)gridDim.x * blockDim.x;
    for (size_t j = (size_t)blockIdx.x * blockDim.x + threadIdx.x; j < n4; j += stride) {
        float4 v = w4[j];
        bool k0, k1, k2, k3;
        if (mode == 0) {
            uchar4 m = ((const uchar4*)mask)[j];
            k0 = m.x; k1 = m.y; k2 = m.z; k3 = m.w;
        } else if (mode == 1) {
            int4 m = ((const int4*)mask)[j];
            k0 = m.x; k1 = m.y; k2 = m.z; k3 = m.w;
        } else {
            float4 m = ((const float4*)mask)[j];
            k0 = m.x != 0.f; k1 = m.y != 0.f; k2 = m.z != 0.f; k3 = m.w != 0.f;
        }
        float a = k0 ? v.x : 0.0f;
        float b = k1 ? v.y : 0.0f;
        float c = k2 ? v.z : 0.0f;
        float d = k3 ? v.w : 0.0f;
        o[2 * j + 0] = __floats2half2_rn(a, b);
        o[2 * j + 1] = __floats2half2_rn(c, d);
    }
}

// ---------------------------------------------------------------------------
// tcgen05-only helpers (compiled on the sm_103a cubin pass)
// ---------------------------------------------------------------------------
#if defined(__CUDA_ARCH_FEAT_SM103_ALL)
__device__ __forceinline__ bool elect_one() {
    uint32_t p;
    asm volatile(
        "{\n\t.reg .pred p;\n\t"
        "elect.sync _|p, 0xFFFFFFFF;\n\t"
        "selp.b32 %0, 1, 0, p;\n\t}"
        : "=r"(p));
    return p != 0;
}
__device__ __forceinline__ void mbar_init(uint32_t mbar, uint32_t cnt) {
    asm volatile("mbarrier.init.shared.b64 [%0], %1;" :: "r"(mbar), "r"(cnt) : "memory");
}
__device__ __forceinline__ void mbar_wait(uint32_t mbar, uint32_t parity) {
    asm volatile(
        "{\n\t.reg .pred P1;\n\t"
        "WAIT_%=:\n\t"
        "mbarrier.try_wait.parity.acquire.cta.shared::cta.b64 P1, [%0], %1, 0x989680;\n\t"
        "@P1 bra.uni DONE_%=;\n\t"
        "bra.uni WAIT_%=;\n\t"
        "DONE_%=:\n\t}"
        :: "r"(mbar), "r"(parity) : "memory");
}
__device__ __forceinline__ uint64_t make_desc_sw128(uint32_t addr) {
    uint64_t d = (uint64_t(2) << 61) | (uint64_t(1) << 46) |
                 (uint64_t(64) << 32) | (uint64_t(1) << 16);
    return d | ((uint64_t)(addr >> 4) & 0x3FFF);
}
#define MMA_IDESC ((1u << 4) | ((BN / 8) << 17) | ((BM / 16) << 24))
#endif

// ---------------------------------------------------------------------------
// GEMM kernel: D[M,N] = A[M,K] @ B[N,K]^T
// ---------------------------------------------------------------------------
#define STAGE_BYTES (BM * 128 + BN * 128)             // 16KB A + 16KB B
#define SMEM_DYN_BYTES (STAGES * STAGE_BYTES + 1024)

__global__ void __launch_bounds__(THREADS)
sparse_gemm_kernel(float* __restrict__ out) {
    extern __shared__ char dsmem[];
    const int tid = threadIdx.x;
    const int wid = tid >> 5;
    const int lid = tid & 31;
    const int nt = blockIdx.x;   // N tile
    const int mt = blockIdx.y;   // M tile

    const uint32_t tiles = (smem_u32(dsmem) + 1023u) & ~1023u;

    const __half* gA_base = g_A + (size_t)mt * BM * KDIM;
    const __half* gB_base = g_B + (size_t)nt * BN * KDIM;

    // Tile loader: 1024 x 16B chunks per operand; SW128 swizzle.
    auto load_tile = [&](int kt, int stage) {
        const uint32_t sA = tiles + stage * STAGE_BYTES;
        const uint32_t sB = sA + BM * 128;
        const __half* gA = gA_base + kt * BK;
        const __half* gB = gB_base + kt * BK;
#pragma unroll
        for (int i = 0; i < 4; i++) {
            int c = tid + i * THREADS;        // 0..1023
            int row = c >> 3;
            int col = c & 7;                  // 16B chunk within 128B row
            uint32_t off = (uint32_t)(row << 7) | (uint32_t)(col << 4);
            uint32_t sw = off ^ ((off >> 3) & 0x70);
            size_t goff = (size_t)row * KDIM + col * 8;
            cp_async16(sA + sw, gA + goff);
            cp_async16(sB + sw, gB + goff);
        }
        asm volatile("cp.async.commit_group;" ::: "memory");
    };

#if defined(__CUDA_ARCH_FEAT_SM103_ALL)
    // ======================= tcgen05 path (sm_103a cubin) ==================
    __shared__ uint64_t s_mbar[STAGES];
    __shared__ uint32_t s_tmem_ptr;

    if (wid == 0) {
        asm volatile("tcgen05.alloc.cta_group::1.sync.aligned.shared::cta.b32 [%0], %1;"
                     :: "r"(smem_u32(&s_tmem_ptr)), "r"(128) : "memory");
        asm volatile("tcgen05.relinquish_alloc_permit.cta_group::1.sync.aligned;");
    }
    if (tid < STAGES) mbar_init(smem_u32(&s_mbar[tid]), 1);
    __syncthreads();

    uint32_t tmem;
    asm volatile("ld.shared.b32 %0, [%1];" : "=r"(tmem) : "r"(smem_u32(&s_tmem_ptr)));

    // Prologue: tiles 0 and 1 staged; tile kt+2 loaded inside iteration kt.
    load_tile(0, 0);
    load_tile(1, 1);

    for (int kt = 0; kt < NKT; kt++) {
        const int s = kt % STAGES;

        // One-tile-lagged MMA wait: before overwriting stage (kt+2)%3 (used
        // by MMA(kt-1)), ensure MMA(kt-1) is done. Overlaps MMA latency with
        // this iteration's cp.async wait.
        if (kt >= 1)
            mbar_wait(smem_u32(&s_mbar[(kt - 1) % STAGES]),
                      (uint32_t)((kt - 1) / STAGES) & 1u);

        if (kt + 2 < NKT) load_tile(kt + 2, (kt + 2) % STAGES);

        // Ensure tile kt's cp.async group completed.
        if (kt < NKT - 2)      asm volatile("cp.async.wait_group 2;" ::: "memory");
        else if (kt == NKT - 2) asm volatile("cp.async.wait_group 1;" ::: "memory");
        else                    asm volatile("cp.async.wait_group 0;" ::: "memory");
        __syncthreads();

        if (wid == 0 && elect_one()) {
            asm volatile("tcgen05.fence::after_thread_sync;" ::: "memory");
            asm volatile("fence.proxy.async.shared::cta;" ::: "memory");
            const uint32_t stage_base = tiles + s * STAGE_BYTES;
            uint64_t ad = make_desc_sw128(stage_base);
            uint64_t bd = make_desc_sw128(stage_base + BM * 128);
#pragma unroll
            for (int s4 = 0; s4 < 4; s4++) {
                uint32_t en = !(kt == 0 && s4 == 0);
                asm volatile(
                    "{\n\t.reg .pred p;\n\t"
                    "setp.ne.u32 p, %4, 0;\n\t"
                    "tcgen05.mma.cta_group::1.kind::f16 [%0], %1, %2, %3, {%5,%5,%5,%5}, p;\n\t}"
                    :: "r"(tmem), "l"(ad + 2 * s4), "l"(bd + 2 * s4),
                       "r"(MMA_IDESC), "r"(en), "r"(0u) : "memory");
            }
            asm volatile(
                "tcgen05.commit.cta_group::1.mbarrier::arrive::one.shared::cluster.b64 [%0];"
                :: "r"(smem_u32(&s_mbar[s])) : "memory");
        }
    }

    // Final MMA completion wait, then epilogue.
    mbar_wait(smem_u32(&s_mbar[(NKT - 1) % STAGES]),
              (uint32_t)((NKT - 1) / STAGES) & 1u);
    asm volatile("tcgen05.fence::after_thread_sync;" ::: "memory");

    if (wid < 4) {
        const int m = mt * BM + wid * 32 + lid;
        float* orow = out + (size_t)m * NDIM + nt * BN;
        uint32_t r[32];
#pragma unroll
        for (int c4 = 0; c4 < 4; c4++) {
            asm volatile(
                "tcgen05.ld.sync.aligned.32x32b.x32.b32 "
                "{%0,%1,%2,%3,%4,%5,%6,%7,%8,%9,%10,%11,%12,%13,%14,%15,"
                "%16,%17,%18,%19,%20,%21,%22,%23,%24,%25,%26,%27,%28,%29,%30,%31}, [%32];"
                : "=r"(r[0]), "=r"(r[1]), "=r"(r[2]), "=r"(r[3]),
                  "=r"(r[4]), "=r"(r[5]), "=r"(r[6]), "=r"(r[7]),
                  "=r"(r[8]), "=r"(r[9]), "=r"(r[10]), "=r"(r[11]),
                  "=r"(r[12]), "=r"(r[13]), "=r"(r[14]), "=r"(r[15]),
                  "=r"(r[16]), "=r"(r[17]), "=r"(r[18]), "=r"(r[19]),
                  "=r"(r[20]), "=r"(r[21]), "=r"(r[22]), "=r"(r[23]),
                  "=r"(r[24]), "=r"(r[25]), "=r"(r[26]), "=r"(r[27]),
                  "=r"(r[28]), "=r"(r[29]), "=r"(r[30]), "=r"(r[31])
                : "r"(tmem + c4 * 32));
            asm volatile("tcgen05.wait::ld.sync.aligned;" ::: "memory");
            float4* p = (float4*)(orow + c4 * 32);
#pragma unroll
            for (int q = 0; q < 8; q++)
                p[q] = make_float4(__uint_as_float(r[4 * q + 0]),
                                   __uint_as_float(r[4 * q + 1]),
                                   __uint_as_float(r[4 * q + 2]),
                                   __uint_as_float(r[4 * q + 3]));
        }
        asm volatile("tcgen05.fence::before_thread_sync;" ::: "memory");
    }
    __syncthreads();
    if (wid == 0)
        asm volatile("tcgen05.dealloc.cta_group::1.sync.aligned.b32 %0, %1;"
                     :: "r"(tmem), "r"(128));

#else
    // ============ mma.sync fallback (compute_103 PTX pass only) ===========
    const int wm = wid & 1;          // 0..1
    const int wn = wid >> 1;         // 0..3
    const int m_base = wm * 64;
    const int n_base = wn * 32;

    float acc[4][4][4];              // [mi][n8][reg]
#pragma unroll
    for (int i = 0; i < 4; i++)
#pragma unroll
        for (int j = 0; j < 4; j++)
#pragma unroll
            for (int q = 0; q < 4; q++) acc[i][j][q] = 0.0f;

    const uint32_t baseA_off = (uint32_t)(m_base + (lid & 15)) * 128u + (uint32_t)(lid >> 4) * 16u;
    const uint32_t baseB_off = (uint32_t)(n_base + ((lid >> 4) << 3) + (lid & 7)) * 128u +
                               (uint32_t)((lid >> 3) & 1) * 16u;

    load_tile(0, 0);
    load_tile(1, 1);

    for (int kt = 0; kt < NKT; kt++) {
        const int stage = kt % STAGES;
        if (kt < NKT - 2) asm volatile("cp.async.wait_group 1;" ::: "memory");
        else              asm volatile("cp.async.wait_group 0;" ::: "memory");
        __syncthreads();

        if (kt + 2 < NKT) load_tile(kt + 2, (kt + 2) % STAGES);

        const uint32_t sA = tiles + stage * STAGE_BYTES;
        const uint32_t sB = sA + BM * 128;

#pragma unroll
        for (int ks = 0; ks < 4; ks++) {
            uint32_t a[4][4];
#pragma unroll
            for (int mi = 0; mi < 4; mi++) {
                uint32_t off = baseA_off + (uint32_t)mi * 2048u + (uint32_t)ks * 32u;
                uint32_t addr = sA + (off ^ ((off >> 3) & 0x70));
                asm volatile("ldmatrix.sync.aligned.m8n8.x4.shared.b16 {%0,%1,%2,%3}, [%4];"
                             : "=r"(a[mi][0]), "=r"(a[mi][1]), "=r"(a[mi][2]), "=r"(a[mi][3])
                             : "r"(addr));
            }
            uint32_t b[2][4];
#pragma unroll
            for (int nj = 0; nj < 2; nj++) {
                uint32_t off = baseB_off + (uint32_t)nj * 2048u + (uint32_t)ks * 32u;
                uint32_t addr = sB + (off ^ ((off >> 3) & 0x70));
                asm volatile("ldmatrix.sync.aligned.m8n8.x4.shared.b16 {%0,%1,%2,%3}, [%4];"
                             : "=r"(b[nj][0]), "=r"(b[nj][1]), "=r"(b[nj][2]), "=r"(b[nj][3])
                             : "r"(addr));
            }
#pragma unroll
            for (int mi = 0; mi < 4; mi++) {
#pragma unroll
                for (int n8 = 0; n8 < 4; n8++) {
                    uint32_t b0 = b[n8 >> 1][(n8 & 1) * 2 + 0];
                    uint32_t b1 = b[n8 >> 1][(n8 & 1) * 2 + 1];
                    asm volatile(
                        "mma.sync.aligned.m16n8k16.row.col.f32.f16.f16.f32 "
                        "{%0,%1,%2,%3}, {%4,%5,%6,%7}, {%8,%9}, {%0,%1,%2,%3};"
                        : "+f"(acc[mi][n8][0]), "+f"(acc[mi][n8][1]),
                          "+f"(acc[mi][n8][2]), "+f"(acc[mi][n8][3])
                        : "r"(a[mi][0]), "r"(a[mi][1]), "r"(a[mi][2]), "r"(a[mi][3]),
                          "r"(b0), "r"(b1));
                }
            }
        }
    }

    const int tg = lid >> 2;            // 0..7
    const int tc = (lid & 3) * 2;
    float* obase = out + (size_t)(mt * BM + m_base) * NDIM + nt * BN + n_base;
#pragma unroll
    for (int mi = 0; mi < 4; mi++) {
#pragma unroll
        for (int n8 = 0; n8 < 4; n8++) {
            int r0 = mi * 16 + tg;
            int c0 = n8 * 8 + tc;
            float2 v0 = make_float2(acc[mi][n8][0], acc[mi][n8][1]);
            float2 v1 = make_float2(acc[mi][n8][2], acc[mi][n8][3]);
            *(float2*)(obase + (size_t)r0 * NDIM + c0) = v0;
            *(float2*)(obase + (size_t)(r0 + 8) * NDIM + c0) = v1;
        }
    }
#endif
}

// ---------------------------------------------------------------------------
// Launch
// ---------------------------------------------------------------------------
extern "C" void kernel_launch(void* const* d_in, const int* in_sizes, int n_in,
                              void* d_out, int out_size) {
    const float* x = (const float*)d_in[0];
    const float* w = (const float*)d_in[1];
    const void* mask = d_in[2];
    float* out = (float*)d_out;

    cudaFuncSetAttribute(sparse_gemm_kernel,
                         cudaFuncAttributeMaxDynamicSharedMemorySize,
                         SMEM_DYN_BYTES);

    detect_mask_kernel<<<1, 256>>>((const uint4*)mask);
    convert_x_kernel<<<4096, 256>>>(x);
    convert_w_kernel<<<2048, 256>>>(w, mask);

    dim3 grid(NDIM / BN, MDIM / BM);  // (32, 64)
    sparse_gemm_kernel<<<grid, THREADS, SMEM_DYN_BYTES>>>(out);
}